// round 2
// baseline (speedup 1.0000x reference)
#include <cuda_runtime.h>
#include <math.h>

#define NN 50000
#define EE_MAX 800000
#define NE_MAX (EE_MAX + NN)
#define IND 512
#define F1 512
#define HID 128
#define HEADS 4
#define OUTD 64
#define NC 4

// ---------------- scratch (device globals; no allocation) ----------------
static __device__ float    g_h1pre[(size_t)NN * F1];
static __device__ float    g_h1agg[(size_t)NN * F1];
static __device__ float    g_as1[NN * HEADS];
static __device__ float    g_ad1[NN * HEADS];
static __device__ unsigned g_m1[NN * HEADS];
static __device__ float    g_s1[NN * HEADS];
static __device__ float    g_ebuf1[(size_t)NE_MAX * HEADS];
static __device__ float    g_h2pre[(size_t)NN * OUTD];
static __device__ float    g_h2agg[(size_t)NN * OUTD];
static __device__ float    g_as2[NN];
static __device__ float    g_ad2[NN];
static __device__ unsigned g_m2[NN];
static __device__ float    g_s2[NN];
static __device__ float    g_ebuf2[NE_MAX];
static __device__ float    g_scores[NN];
static __device__ unsigned g_gmax;
static __device__ float    g_gsum;
static __device__ float    g_cn[NC * OUTD];

// ---------------- helpers ----------------
__device__ __forceinline__ float leaky02(float x) { return x > 0.f ? x : 0.2f * x; }

// order-preserving float<->uint encoding for atomicMax on floats
__device__ __forceinline__ unsigned fenc(float f) {
    unsigned u = __float_as_uint(f);
    return (u & 0x80000000u) ? ~u : (u | 0x80000000u);
}
__device__ __forceinline__ float fdec(unsigned u) {
    return __uint_as_float((u & 0x80000000u) ? (u & 0x7fffffffu) : ~u);
}
#define ENC_NEGINF 0x007fffffu  // fenc(-inf)

__device__ __forceinline__ float warp_sum(float v) {
#pragma unroll
    for (int o = 16; o; o >>= 1) v += __shfl_xor_sync(0xffffffffu, v, o);
    return v;
}

// ---------------- init ----------------
__global__ void k_init() {
    size_t i = (size_t)blockIdx.x * blockDim.x + threadIdx.x;
    if (i < (size_t)NN * F1) g_h1agg[i] = 0.f;
    if (i < (size_t)NN * OUTD) g_h2agg[i] = 0.f;
    if (i < (size_t)NN * HEADS) { g_m1[i] = ENC_NEGINF; g_s1[i] = 0.f; }
    if (i < NN) { g_m2[i] = ENC_NEGINF; g_s2[i] = 0.f; }
    if (i == 0) { g_gmax = ENC_NEGINF; g_gsum = 0.f; }
}

// normalize class_attn rows -> g_cn  (1 block, 128 threads: warp r handles row r)
__global__ void k_cn(const float* __restrict__ ca) {
    int r = threadIdx.x >> 5, lane = threadIdx.x & 31;
    float ss = 0.f;
    for (int i = lane; i < OUTD; i += 32) { float v = ca[r * OUTD + i]; ss += v * v; }
    ss = warp_sum(ss);
    float inv = 1.f / fmaxf(sqrtf(ss), 1e-12f);
    for (int i = lane; i < OUTD; i += 32) g_cn[r * OUTD + i] = ca[r * OUTD + i] * inv;
}

// ---------------- tiled fp32 GEMM: C[M,N] = A[M,K] @ B[K,N] ----------------
// BM=128, BN=64, BK=16, 256 threads, 8x4 per-thread microtile.
__device__ __forceinline__ void gemm_body(const float* __restrict__ A,
                                          const float* __restrict__ B,
                                          float* __restrict__ C,
                                          int M, int N, int K) {
    __shared__ float As[16][128];
    __shared__ float Bs[16][64];
    const int tid = threadIdx.x;
    const int row0 = blockIdx.y * 128;
    const int col0 = blockIdx.x * 64;
    const int tx = tid & 15;
    const int ty = tid >> 4;
    float acc[8][4];
#pragma unroll
    for (int i = 0; i < 8; i++)
#pragma unroll
        for (int j = 0; j < 4; j++) acc[i][j] = 0.f;

    for (int k0 = 0; k0 < K; k0 += 16) {
#pragma unroll
        for (int li = 0; li < 2; li++) {
            int q = tid + li * 256;
            int r = q >> 2;
            int c = (q & 3) << 2;
            float4 v = make_float4(0.f, 0.f, 0.f, 0.f);
            int gr = row0 + r;
            if (gr < M) v = *reinterpret_cast<const float4*>(A + (size_t)gr * K + k0 + c);
            As[c + 0][r] = v.x; As[c + 1][r] = v.y; As[c + 2][r] = v.z; As[c + 3][r] = v.w;
        }
        {
            int r = tid >> 4;
            int c = (tid & 15) << 2;
            float4 v = *reinterpret_cast<const float4*>(B + (size_t)(k0 + r) * N + col0 + c);
            *reinterpret_cast<float4*>(&Bs[r][c]) = v;
        }
        __syncthreads();
#pragma unroll
        for (int k = 0; k < 16; k++) {
            float ra[8], rb[4];
#pragma unroll
            for (int i = 0; i < 8; i++) ra[i] = As[k][ty * 8 + i];
#pragma unroll
            for (int j = 0; j < 4; j++) rb[j] = Bs[k][tx * 4 + j];
#pragma unroll
            for (int i = 0; i < 8; i++)
#pragma unroll
                for (int j = 0; j < 4; j++) acc[i][j] = fmaf(ra[i], rb[j], acc[i][j]);
        }
        __syncthreads();
    }
#pragma unroll
    for (int i = 0; i < 8; i++) {
        int gr = row0 + ty * 8 + i;
        if (gr < M) {
            float4 v = make_float4(acc[i][0], acc[i][1], acc[i][2], acc[i][3]);
            *reinterpret_cast<float4*>(C + (size_t)gr * N + col0 + tx * 4) = v;
        }
    }
}

__global__ void k_gemm1(const float* __restrict__ A, const float* __restrict__ B) {
    gemm_body(A, B, g_h1pre, NN, F1, IND);
}
__global__ void k_gemm2(const float* __restrict__ B) {
    gemm_body(g_h1agg, B, g_h2pre, NN, OUTD, F1);
}

// ---------------- per-node attention coefficients ----------------
// layer1: one block per node, warp w -> head w
__global__ void k_att1(const float* __restrict__ att_src, const float* __restrict__ att_dst) {
    int n = blockIdx.x;
    int w = threadIdx.x >> 5, lane = threadIdx.x & 31;
    const float* row = &g_h1pre[(size_t)n * F1 + w * HID];
    const float* as = att_src + w * HID;
    const float* ad = att_dst + w * HID;
    float s = 0.f, d = 0.f;
#pragma unroll
    for (int i = lane; i < HID; i += 32) {
        float v = row[i];
        s += v * __ldg(&as[i]);
        d += v * __ldg(&ad[i]);
    }
    s = warp_sum(s);
    d = warp_sum(d);
    if (lane == 0) { g_as1[n * 4 + w] = s; g_ad1[n * 4 + w] = d; }
}

// layer2: warp per node (8 nodes per 256-thread block)
__global__ void k_att2(const float* __restrict__ att_src, const float* __restrict__ att_dst) {
    int n = blockIdx.x * (blockDim.x >> 5) + (threadIdx.x >> 5);
    int lane = threadIdx.x & 31;
    if (n >= NN) return;
    const float* row = &g_h2pre[(size_t)n * OUTD];
    float s = 0.f, d = 0.f;
#pragma unroll
    for (int i = lane; i < OUTD; i += 32) {
        float v = row[i];
        s += v * __ldg(&att_src[i]);
        d += v * __ldg(&att_dst[i]);
    }
    s = warp_sum(s);
    d = warp_sum(d);
    if (lane == 0) { g_as2[n] = s; g_ad2[n] = d; }
}

// ---------------- layer-1 edge passes ----------------
__device__ __forceinline__ void edge_sd(const int* ei, int e, int E, int& s, int& d) {
    if (e < E) { s = ei[e]; d = ei[E + e]; }
    else       { s = d = e - E; }
}

__global__ void k_emax1(const int* __restrict__ ei, int E, int NE) {
    int e = blockIdx.x * blockDim.x + threadIdx.x;
    if (e >= NE) return;
    int s, d; edge_sd(ei, e, E, s, d);
    float4 a = *reinterpret_cast<const float4*>(&g_as1[s * 4]);
    float4 b = *reinterpret_cast<const float4*>(&g_ad1[d * 4]);
    float4 ev = make_float4(leaky02(a.x + b.x), leaky02(a.y + b.y),
                            leaky02(a.z + b.z), leaky02(a.w + b.w));
    *reinterpret_cast<float4*>(&g_ebuf1[(size_t)e * 4]) = ev;
    atomicMax(&g_m1[d * 4 + 0], fenc(ev.x));
    atomicMax(&g_m1[d * 4 + 1], fenc(ev.y));
    atomicMax(&g_m1[d * 4 + 2], fenc(ev.z));
    atomicMax(&g_m1[d * 4 + 3], fenc(ev.w));
}

__global__ void k_esum1(const int* __restrict__ ei, int E, int NE) {
    int e = blockIdx.x * blockDim.x + threadIdx.x;
    if (e >= NE) return;
    int s, d; edge_sd(ei, e, E, s, d);
    float4 ev = *reinterpret_cast<const float4*>(&g_ebuf1[(size_t)e * 4]);
    uint4 mu = *reinterpret_cast<const uint4*>(&g_m1[d * 4]);
    float4 ex = make_float4(expf(ev.x - fdec(mu.x)), expf(ev.y - fdec(mu.y)),
                            expf(ev.z - fdec(mu.z)), expf(ev.w - fdec(mu.w)));
    *reinterpret_cast<float4*>(&g_ebuf1[(size_t)e * 4]) = ex;
    atomicAdd(&g_s1[d * 4 + 0], ex.x);
    atomicAdd(&g_s1[d * 4 + 1], ex.y);
    atomicAdd(&g_s1[d * 4 + 2], ex.z);
    atomicAdd(&g_s1[d * 4 + 3], ex.w);
}

// one 128-thread block per edge; thread t handles floats [4t,4t+4), head = t/32
__global__ void k_emsg1(const int* __restrict__ ei, int E, int NE) {
    __shared__ int sh_s, sh_d;
    __shared__ float sh_alpha[HEADS];
    int e = blockIdx.x;
    if (e >= NE) return;
    int t = threadIdx.x;
    if (t == 0) {
        int s, d; edge_sd(ei, e, E, s, d);
        sh_s = s; sh_d = d;
    }
    if (t < HEADS) {
        int d = (e < E) ? ei[E + e] : (e - E);
        sh_alpha[t] = g_ebuf1[(size_t)e * 4 + t] / (g_s1[d * 4 + t] + 1e-16f);
    }
    __syncthreads();
    int s = sh_s, d = sh_d;
    int h = t >> 5;
    float alpha = sh_alpha[h];
    float4 v = *reinterpret_cast<const float4*>(&g_h1pre[(size_t)s * F1 + 4 * t]);
    float* dst = &g_h1agg[(size_t)d * F1 + 4 * t];
    atomicAdd(dst + 0, v.x * alpha);
    atomicAdd(dst + 1, v.y * alpha);
    atomicAdd(dst + 2, v.z * alpha);
    atomicAdd(dst + 3, v.w * alpha);
}

__global__ void k_elubias(const float* __restrict__ b1) {
    size_t i = (size_t)blockIdx.x * blockDim.x + threadIdx.x;
    if (i >= (size_t)NN * F1) return;
    float v = g_h1agg[i] + __ldg(&b1[i & (F1 - 1)]);
    g_h1agg[i] = v > 0.f ? v : expm1f(v);
}

// ---------------- layer-2 edge passes (1 head) ----------------
__global__ void k_emax2(const int* __restrict__ ei, int E, int NE) {
    int e = blockIdx.x * blockDim.x + threadIdx.x;
    if (e >= NE) return;
    int s, d; edge_sd(ei, e, E, s, d);
    float ev = leaky02(g_as2[s] + g_ad2[d]);
    g_ebuf2[e] = ev;
    atomicMax(&g_m2[d], fenc(ev));
}

__global__ void k_esum2(const int* __restrict__ ei, int E, int NE) {
    int e = blockIdx.x * blockDim.x + threadIdx.x;
    if (e >= NE) return;
    int s, d; edge_sd(ei, e, E, s, d);
    float ex = expf(g_ebuf2[e] - fdec(g_m2[d]));
    g_ebuf2[e] = ex;
    atomicAdd(&g_s2[d], ex);
}

// warp per edge; lane handles float2 at 2*lane
__global__ void k_emsg2(const int* __restrict__ ei, int E, int NE) {
    int e = blockIdx.x * (blockDim.x >> 5) + (threadIdx.x >> 5);
    if (e >= NE) return;
    int lane = threadIdx.x & 31;
    int s, d; edge_sd(ei, e, E, s, d);
    float alpha = g_ebuf2[e] / (g_s2[d] + 1e-16f);
    float2 v = *reinterpret_cast<const float2*>(&g_h2pre[(size_t)s * OUTD + 2 * lane]);
    float* dst = &g_h2agg[(size_t)d * OUTD + 2 * lane];
    atomicAdd(dst + 0, v.x * alpha);
    atomicAdd(dst + 1, v.y * alpha);
}

__global__ void k_bias2(const float* __restrict__ b2) {
    size_t i = (size_t)blockIdx.x * blockDim.x + threadIdx.x;
    if (i >= (size_t)NN * OUTD) return;
    g_h2agg[i] += __ldg(&b2[i & (OUTD - 1)]);
}

// ---------------- intra-attention scores: tanh(h2@Wa+ba)@wv+bv ----------------
__global__ void k_scores(const float* __restrict__ Wa, const float* __restrict__ ba,
                         const float* __restrict__ wv, const float* __restrict__ bv) {
    int n = blockIdx.x * blockDim.x + threadIdx.x;
    if (n >= NN) return;
    float h[OUTD];
    const float4* row = reinterpret_cast<const float4*>(&g_h2agg[(size_t)n * OUTD]);
#pragma unroll
    for (int i = 0; i < OUTD / 4; i++) {
        float4 v = row[i];
        h[4 * i] = v.x; h[4 * i + 1] = v.y; h[4 * i + 2] = v.z; h[4 * i + 3] = v.w;
    }
    float acc = __ldg(&bv[0]);
    for (int j = 0; j < OUTD; j++) {
        float t = __ldg(&ba[j]);
#pragma unroll
        for (int k = 0; k < OUTD; k++) t = fmaf(h[k], __ldg(&Wa[k * OUTD + j]), t);
        acc = fmaf(tanhf(t), __ldg(&wv[j]), acc);
    }
    g_scores[n] = acc;
}

__global__ void k_rmax() {
    __shared__ float sm[256];
    int tid = threadIdx.x;
    float m = -INFINITY;
    for (int i = blockIdx.x * 256 + tid; i < NN; i += gridDim.x * 256)
        m = fmaxf(m, g_scores[i]);
    sm[tid] = m;
    __syncthreads();
    for (int o = 128; o; o >>= 1) {
        if (tid < o) sm[tid] = fmaxf(sm[tid], sm[tid + o]);
        __syncthreads();
    }
    if (tid == 0) atomicMax(&g_gmax, fenc(sm[0]));
}

__global__ void k_rsum() {
    __shared__ float sm[256];
    int tid = threadIdx.x;
    float M = fdec(g_gmax);
    float s = 0.f;
    for (int i = blockIdx.x * 256 + tid; i < NN; i += gridDim.x * 256)
        s += expf(g_scores[i] - M);
    sm[tid] = s;
    __syncthreads();
    for (int o = 128; o; o >>= 1) {
        if (tid < o) sm[tid] += sm[tid + o];
        __syncthreads();
    }
    if (tid == 0) atomicAdd(&g_gsum, sm[0]);
}

// ---------------- epilogue: xw, out, inter_class_scores ----------------
// out layout: [0, NN*NC) = out ; [NN*NC, NN*NC+NN*64) = xw ; then inter [NN*NC]
__global__ void k_final(const float* __restrict__ Wc, const float* __restrict__ bc,
                        float* __restrict__ out) {
    int n = blockIdx.x * blockDim.x + threadIdx.x;
    if (n >= NN) return;
    float M = fdec(g_gmax);
    float S = g_gsum;
    float attw = expf(g_scores[n] - M) / S;
    float xw[OUTD];
    const float4* row = reinterpret_cast<const float4*>(&g_h2agg[(size_t)n * OUTD]);
    float* oxw = out + (size_t)NN * NC + (size_t)n * OUTD;
    float nrm = 0.f;
#pragma unroll
    for (int i = 0; i < OUTD / 4; i++) {
        float4 v = row[i];
        v.x *= attw; v.y *= attw; v.z *= attw; v.w *= attw;
        xw[4 * i] = v.x; xw[4 * i + 1] = v.y; xw[4 * i + 2] = v.z; xw[4 * i + 3] = v.w;
        nrm += v.x * v.x + v.y * v.y + v.z * v.z + v.w * v.w;
        *reinterpret_cast<float4*>(&oxw[4 * i]) = v;
    }
    float inv = 1.f / fmaxf(sqrtf(nrm), 1e-12f);
#pragma unroll
    for (int c = 0; c < NC; c++) {
        float o = __ldg(&bc[c]);
        float ic = 0.f;
#pragma unroll
        for (int k = 0; k < OUTD; k++) {
            o = fmaf(xw[k], __ldg(&Wc[k * NC + c]), o);
            ic = fmaf(xw[k], g_cn[c * OUTD + k], ic);
        }
        out[(size_t)n * NC + c] = o;
        out[(size_t)NN * NC + (size_t)NN * OUTD + (size_t)n * NC + c] = ic * inv;
    }
}

// ---------------- launch ----------------
extern "C" void kernel_launch(void* const* d_in, const int* in_sizes, int n_in,
                              void* d_out, int out_size) {
    const float* x   = (const float*)d_in[0];
    const int*   ei  = (const int*)d_in[1];
    const float* W1  = (const float*)d_in[2];
    const float* as1 = (const float*)d_in[3];
    const float* ad1 = (const float*)d_in[4];
    const float* b1  = (const float*)d_in[5];
    const float* W2  = (const float*)d_in[6];
    const float* as2 = (const float*)d_in[7];
    const float* ad2 = (const float*)d_in[8];
    const float* b2  = (const float*)d_in[9];
    const float* Wa  = (const float*)d_in[10];
    const float* ba  = (const float*)d_in[11];
    const float* wv  = (const float*)d_in[12];
    const float* bv  = (const float*)d_in[13];
    const float* ca  = (const float*)d_in[14];
    const float* Wc  = (const float*)d_in[15];
    const float* bc  = (const float*)d_in[16];
    float* out = (float*)d_out;

    int E  = in_sizes[1] / 2;
    int NE = E + NN;

    k_init<<<(NN * F1 + 255) / 256, 256>>>();
    k_cn<<<1, 128>>>(ca);

    {
        dim3 g(F1 / 64, (NN + 127) / 128);
        k_gemm1<<<g, 256>>>(x, W1);
    }
    k_att1<<<NN, 128>>>(as1, ad1);
    k_emax1<<<(NE + 255) / 256, 256>>>(ei, E, NE);
    k_esum1<<<(NE + 255) / 256, 256>>>(ei, E, NE);
    k_emsg1<<<NE, 128>>>(ei, E, NE);
    k_elubias<<<(NN * F1 + 255) / 256, 256>>>(b1);

    {
        dim3 g(OUTD / 64, (NN + 127) / 128);
        k_gemm2<<<g, 256>>>(W2);
    }
    k_att2<<<(NN + 7) / 8, 256>>>(as2, ad2);
    k_emax2<<<(NE + 255) / 256, 256>>>(ei, E, NE);
    k_esum2<<<(NE + 255) / 256, 256>>>(ei, E, NE);
    k_emsg2<<<(NE + 7) / 8, 256>>>(ei, E, NE);
    k_bias2<<<(NN * OUTD + 255) / 256, 256>>>(b2);

    k_scores<<<(NN + 127) / 128, 128>>>(Wa, ba, wv, bv);
    k_rmax<<<64, 256>>>();
    k_rsum<<<64, 256>>>();
    k_final<<<(NN + 127) / 128, 128>>>(Wc, bc, out);
}

// round 4
// speedup vs baseline: 2.0493x; 2.0493x over previous
#include <cuda_runtime.h>
#include <math.h>

#define NN 50000
#define EE_MAX 800000
#define NE_MAX (EE_MAX + NN)
#define IND 512
#define F1 512
#define HID 128
#define HEADS 4
#define OUTD 64
#define NC 4

// ---------------- scratch (device globals; no allocation) ----------------
static __device__ float    g_h1pre[(size_t)NN * F1];
static __device__ float    g_h1agg[(size_t)NN * F1];
static __device__ float    g_as1[NN * HEADS];
static __device__ float    g_ad1[NN * HEADS];
static __device__ float    g_h2pre[(size_t)NN * OUTD];
static __device__ float    g_h2agg[(size_t)NN * OUTD];
static __device__ float    g_as2[NN];
static __device__ float    g_ad2[NN];
static __device__ float    g_scores[NN];
static __device__ unsigned g_gmax;
static __device__ float    g_gsum;
static __device__ float    g_cn[NC * OUTD];
// CSR (built per launch; graph identical for both layers)
static __device__ int      g_deg[NN];
static __device__ int      g_rowptr[NN];
static __device__ int      g_cursor[NN];
static __device__ int      g_csr_src[NE_MAX];

// ---------------- helpers ----------------
__device__ __forceinline__ float leaky02(float x) { return x > 0.f ? x : 0.2f * x; }

__device__ __forceinline__ unsigned fenc(float f) {
    unsigned u = __float_as_uint(f);
    return (u & 0x80000000u) ? ~u : (u | 0x80000000u);
}
__device__ __forceinline__ float fdec(unsigned u) {
    return __uint_as_float((u & 0x80000000u) ? (u & 0x7fffffffu) : ~u);
}
#define ENC_NEGINF 0x007fffffu

__device__ __forceinline__ float warp_sum(float v) {
#pragma unroll
    for (int o = 16; o; o >>= 1) v += __shfl_xor_sync(0xffffffffu, v, o);
    return v;
}

__device__ __forceinline__ void edge_sd(const int* ei, int e, int E, int& s, int& d) {
    if (e < E) { s = ei[e]; d = ei[E + e]; }
    else       { s = d = e - E; }
}

// ---------------- init (tiny now: deg + global-softmax scalars) ----------------
__global__ void k_init() {
    int i = blockIdx.x * blockDim.x + threadIdx.x;
    if (i < NN) g_deg[i] = 0;
    if (i == 0) { g_gmax = ENC_NEGINF; g_gsum = 0.f; }
}

__global__ void k_cn(const float* __restrict__ ca) {
    int r = threadIdx.x >> 5, lane = threadIdx.x & 31;
    float ss = 0.f;
    for (int i = lane; i < OUTD; i += 32) { float v = ca[r * OUTD + i]; ss += v * v; }
    ss = warp_sum(ss);
    float inv = 1.f / fmaxf(sqrtf(ss), 1e-12f);
    for (int i = lane; i < OUTD; i += 32) g_cn[r * OUTD + i] = ca[r * OUTD + i] * inv;
}

// ---------------- CSR build ----------------
__global__ void k_deg(const int* __restrict__ ei, int E, int NE) {
    int e = blockIdx.x * blockDim.x + threadIdx.x;
    if (e >= NE) return;
    int d = (e < E) ? ei[E + e] : (e - E);
    atomicAdd(&g_deg[d], 1);
}

// single block, 1024 threads: exclusive scan of g_deg -> g_rowptr/g_cursor
__global__ void k_scan() {
    __shared__ int sh_w[32];
    __shared__ int sh_carry;
    int t = threadIdx.x, lane = t & 31, wid = t >> 5;
    if (t == 0) sh_carry = 0;
    __syncthreads();
    for (int base = 0; base < NN; base += 1024) {
        int i = base + t;
        int v = (i < NN) ? g_deg[i] : 0;
        int x = v;
#pragma unroll
        for (int o = 1; o < 32; o <<= 1) {
            int y = __shfl_up_sync(0xffffffffu, x, o);
            if (lane >= o) x += y;
        }
        if (lane == 31) sh_w[wid] = x;
        __syncthreads();
        if (wid == 0) {
            int wv = sh_w[lane];
            int wx = wv;
#pragma unroll
            for (int o = 1; o < 32; o <<= 1) {
                int y = __shfl_up_sync(0xffffffffu, wx, o);
                if (lane >= o) wx += y;
            }
            sh_w[lane] = wx - wv;  // exclusive warp offset
        }
        __syncthreads();
        int excl_local = x - v + sh_w[wid];
        int excl = excl_local + sh_carry;
        if (i < NN) { g_rowptr[i] = excl; g_cursor[i] = excl; }
        __syncthreads();
        if (t == 1023) sh_carry += excl_local + v;
        __syncthreads();
    }
}

__global__ void k_scatter(const int* __restrict__ ei, int E, int NE) {
    int e = blockIdx.x * blockDim.x + threadIdx.x;
    if (e >= NE) return;
    int s, d; edge_sd(ei, e, E, s, d);
    int pos = atomicAdd(&g_cursor[d], 1);
    g_csr_src[pos] = s;
}

// ---------------- tiled fp32 GEMM: C[M,N] = A[M,K] @ B[K,N] ----------------
__device__ __forceinline__ void gemm_body(const float* __restrict__ A,
                                          const float* __restrict__ B,
                                          float* __restrict__ C,
                                          int M, int N, int K) {
    __shared__ float As[16][128];
    __shared__ float Bs[16][64];
    const int tid = threadIdx.x;
    const int row0 = blockIdx.y * 128;
    const int col0 = blockIdx.x * 64;
    const int tx = tid & 15;
    const int ty = tid >> 4;
    float acc[8][4];
#pragma unroll
    for (int i = 0; i < 8; i++)
#pragma unroll
        for (int j = 0; j < 4; j++) acc[i][j] = 0.f;

    for (int k0 = 0; k0 < K; k0 += 16) {
#pragma unroll
        for (int li = 0; li < 2; li++) {
            int q = tid + li * 256;
            int r = q >> 2;
            int c = (q & 3) << 2;
            float4 v = make_float4(0.f, 0.f, 0.f, 0.f);
            int gr = row0 + r;
            if (gr < M) v = *reinterpret_cast<const float4*>(A + (size_t)gr * K + k0 + c);
            As[c + 0][r] = v.x; As[c + 1][r] = v.y; As[c + 2][r] = v.z; As[c + 3][r] = v.w;
        }
        {
            int r = tid >> 4;
            int c = (tid & 15) << 2;
            float4 v = *reinterpret_cast<const float4*>(B + (size_t)(k0 + r) * N + col0 + c);
            *reinterpret_cast<float4*>(&Bs[r][c]) = v;
        }
        __syncthreads();
#pragma unroll
        for (int k = 0; k < 16; k++) {
            float ra[8], rb[4];
#pragma unroll
            for (int i = 0; i < 8; i++) ra[i] = As[k][ty * 8 + i];
#pragma unroll
            for (int j = 0; j < 4; j++) rb[j] = Bs[k][tx * 4 + j];
#pragma unroll
            for (int i = 0; i < 8; i++)
#pragma unroll
                for (int j = 0; j < 4; j++) acc[i][j] = fmaf(ra[i], rb[j], acc[i][j]);
        }
        __syncthreads();
    }
#pragma unroll
    for (int i = 0; i < 8; i++) {
        int gr = row0 + ty * 8 + i;
        if (gr < M) {
            float4 v = make_float4(acc[i][0], acc[i][1], acc[i][2], acc[i][3]);
            *reinterpret_cast<float4*>(C + (size_t)gr * N + col0 + tx * 4) = v;
        }
    }
}

__global__ void k_gemm1(const float* __restrict__ A, const float* __restrict__ B) {
    gemm_body(A, B, g_h1pre, NN, F1, IND);
}
__global__ void k_gemm2(const float* __restrict__ B) {
    gemm_body(g_h1agg, B, g_h2pre, NN, OUTD, F1);
}

// ---------------- per-node attention coefficients ----------------
__global__ void k_att1(const float* __restrict__ att_src, const float* __restrict__ att_dst) {
    int n = blockIdx.x;
    int w = threadIdx.x >> 5, lane = threadIdx.x & 31;
    const float* row = &g_h1pre[(size_t)n * F1 + w * HID];
    const float* as = att_src + w * HID;
    const float* ad = att_dst + w * HID;
    float s = 0.f, d = 0.f;
#pragma unroll
    for (int i = lane; i < HID; i += 32) {
        float v = row[i];
        s += v * __ldg(&as[i]);
        d += v * __ldg(&ad[i]);
    }
    s = warp_sum(s);
    d = warp_sum(d);
    if (lane == 0) { g_as1[n * 4 + w] = s; g_ad1[n * 4 + w] = d; }
}

__global__ void k_att2(const float* __restrict__ att_src, const float* __restrict__ att_dst) {
    int n = blockIdx.x * (blockDim.x >> 5) + (threadIdx.x >> 5);
    int lane = threadIdx.x & 31;
    if (n >= NN) return;
    const float* row = &g_h2pre[(size_t)n * OUTD];
    float s = 0.f, d = 0.f;
#pragma unroll
    for (int i = lane; i < OUTD; i += 32) {
        float v = row[i];
        s += v * __ldg(&att_src[i]);
        d += v * __ldg(&att_dst[i]);
    }
    s = warp_sum(s);
    d = warp_sum(d);
    if (lane == 0) { g_as2[n] = s; g_ad2[n] = d; }
}

// ---------------- layer 1 fused aggregation (per-dst gather, no atomics) ----------------
// block = 128 threads, one dst node per block. warp h owns head h.
// Phase A: online softmax over incoming edges per head.
// Phase B: tiled alpha-weighted gather of h1pre rows; bias + ELU fused on store.
__global__ void k_agg1(const float* __restrict__ b1) {
    __shared__ int   sh_src[32];
    __shared__ float sh_al[32 * HEADS];
    int d = blockIdx.x;
    int t = threadIdx.x, h = t >> 5, lane = t & 31;
    int beg = g_rowptr[d], cnt = g_deg[d];
    float ad_h = g_ad1[d * 4 + h];

    // Phase A (per warp / per head)
    float m = -1e30f, s = 0.f;
    for (int i = lane; i < cnt; i += 32) {
        int src = g_csr_src[beg + i];
        float e = leaky02(g_as1[src * 4 + h] + ad_h);
        float nm = fmaxf(m, e);
        s = s * expf(m - nm) + expf(e - nm);
        m = nm;
    }
#pragma unroll
    for (int o = 16; o; o >>= 1) {
        float mo = __shfl_xor_sync(0xffffffffu, m, o);
        float so = __shfl_xor_sync(0xffffffffu, s, o);
        float nm = fmaxf(m, mo);
        s = s * expf(m - nm) + so * expf(mo - nm);
        m = nm;
    }
    float inv = 1.f / (s + 1e-16f);

    // Phase B: tiles of 32 edges
    float4 acc = make_float4(0.f, 0.f, 0.f, 0.f);
    for (int base = 0; base < cnt; base += 32) {
        int nt = min(32, cnt - base);
        if (lane < nt) {
            int src_l = g_csr_src[beg + base + lane];
            float e = leaky02(g_as1[src_l * 4 + h] + ad_h);
            sh_al[lane * HEADS + h] = expf(e - m) * inv;
            if (h == 0) sh_src[lane] = src_l;
        }
        __syncthreads();
#pragma unroll 4
        for (int j = 0; j < nt; j++) {
            int src = sh_src[j];
            float a = sh_al[j * HEADS + h];
            float4 v = *reinterpret_cast<const float4*>(&g_h1pre[(size_t)src * F1 + 4 * t]);
            acc.x = fmaf(a, v.x, acc.x);
            acc.y = fmaf(a, v.y, acc.y);
            acc.z = fmaf(a, v.z, acc.z);
            acc.w = fmaf(a, v.w, acc.w);
        }
        __syncthreads();
    }

    // bias + ELU, store
    float4 bb = *reinterpret_cast<const float4*>(&b1[4 * t]);
    float o0 = acc.x + bb.x, o1 = acc.y + bb.y, o2 = acc.z + bb.z, o3 = acc.w + bb.w;
    o0 = o0 > 0.f ? o0 : expm1f(o0);
    o1 = o1 > 0.f ? o1 : expm1f(o1);
    o2 = o2 > 0.f ? o2 : expm1f(o2);
    o3 = o3 > 0.f ? o3 : expm1f(o3);
    *reinterpret_cast<float4*>(&g_h1agg[(size_t)d * F1 + 4 * t]) =
        make_float4(o0, o1, o2, o3);
}

// ---------------- layer 2 fused aggregation: warp per dst ----------------
__global__ void k_agg2(const float* __restrict__ b2) {
    int w = (blockIdx.x * blockDim.x + threadIdx.x) >> 5;
    int lane = threadIdx.x & 31;
    if (w >= NN) return;
    int beg = g_rowptr[w], cnt = g_deg[w];
    float ad = g_ad2[w];

    float m = -1e30f, s = 0.f;
    for (int i = lane; i < cnt; i += 32) {
        int src = g_csr_src[beg + i];
        float e = leaky02(g_as2[src] + ad);
        float nm = fmaxf(m, e);
        s = s * expf(m - nm) + expf(e - nm);
        m = nm;
    }
#pragma unroll
    for (int o = 16; o; o >>= 1) {
        float mo = __shfl_xor_sync(0xffffffffu, m, o);
        float so = __shfl_xor_sync(0xffffffffu, s, o);
        float nm = fmaxf(m, mo);
        s = s * expf(m - nm) + so * expf(mo - nm);
        m = nm;
    }
    float inv = 1.f / (s + 1e-16f);

    float2 acc = make_float2(0.f, 0.f);
    for (int i = 0; i < cnt; i++) {
        int src = g_csr_src[beg + i];                 // broadcast
        float e = leaky02(g_as2[src] + ad);           // broadcast
        float a = expf(e - m) * inv;
        float2 v = *reinterpret_cast<const float2*>(&g_h2pre[(size_t)src * OUTD + 2 * lane]);
        acc.x = fmaf(a, v.x, acc.x);
        acc.y = fmaf(a, v.y, acc.y);
    }
    float2 bb = *reinterpret_cast<const float2*>(&b2[2 * lane]);
    *reinterpret_cast<float2*>(&g_h2agg[(size_t)w * OUTD + 2 * lane]) =
        make_float2(acc.x + bb.x, acc.y + bb.y);
}

// ---------------- intra-attention scores ----------------
__global__ void k_scores(const float* __restrict__ Wa, const float* __restrict__ ba,
                         const float* __restrict__ wv, const float* __restrict__ bv) {
    int n = blockIdx.x * blockDim.x + threadIdx.x;
    if (n >= NN) return;
    float h[OUTD];
    const float4* row = reinterpret_cast<const float4*>(&g_h2agg[(size_t)n * OUTD]);
#pragma unroll
    for (int i = 0; i < OUTD / 4; i++) {
        float4 v = row[i];
        h[4 * i] = v.x; h[4 * i + 1] = v.y; h[4 * i + 2] = v.z; h[4 * i + 3] = v.w;
    }
    float acc = __ldg(&bv[0]);
    for (int j = 0; j < OUTD; j++) {
        float t = __ldg(&ba[j]);
#pragma unroll
        for (int k = 0; k < OUTD; k++) t = fmaf(h[k], __ldg(&Wa[k * OUTD + j]), t);
        acc = fmaf(tanhf(t), __ldg(&wv[j]), acc);
    }
    g_scores[n] = acc;
}

__global__ void k_rmax() {
    __shared__ float sm[256];
    int tid = threadIdx.x;
    float m = -INFINITY;
    for (int i = blockIdx.x * 256 + tid; i < NN; i += gridDim.x * 256)
        m = fmaxf(m, g_scores[i]);
    sm[tid] = m;
    __syncthreads();
    for (int o = 128; o; o >>= 1) {
        if (tid < o) sm[tid] = fmaxf(sm[tid], sm[tid + o]);
        __syncthreads();
    }
    if (tid == 0) atomicMax(&g_gmax, fenc(sm[0]));
}

__global__ void k_rsum() {
    __shared__ float sm[256];
    int tid = threadIdx.x;
    float M = fdec(g_gmax);
    float s = 0.f;
    for (int i = blockIdx.x * 256 + tid; i < NN; i += gridDim.x * 256)
        s += expf(g_scores[i] - M);
    sm[tid] = s;
    __syncthreads();
    for (int o = 128; o; o >>= 1) {
        if (tid < o) sm[tid] += sm[tid + o];
        __syncthreads();
    }
    if (tid == 0) atomicAdd(&g_gsum, sm[0]);
}

// ---------------- epilogue ----------------
__global__ void k_final(const float* __restrict__ Wc, const float* __restrict__ bc,
                        float* __restrict__ out) {
    int n = blockIdx.x * blockDim.x + threadIdx.x;
    if (n >= NN) return;
    float M = fdec(g_gmax);
    float S = g_gsum;
    float attw = expf(g_scores[n] - M) / S;
    float xw[OUTD];
    const float4* row = reinterpret_cast<const float4*>(&g_h2agg[(size_t)n * OUTD]);
    float* oxw = out + (size_t)NN * NC + (size_t)n * OUTD;
    float nrm = 0.f;
#pragma unroll
    for (int i = 0; i < OUTD / 4; i++) {
        float4 v = row[i];
        v.x *= attw; v.y *= attw; v.z *= attw; v.w *= attw;
        xw[4 * i] = v.x; xw[4 * i + 1] = v.y; xw[4 * i + 2] = v.z; xw[4 * i + 3] = v.w;
        nrm += v.x * v.x + v.y * v.y + v.z * v.z + v.w * v.w;
        *reinterpret_cast<float4*>(&oxw[4 * i]) = v;
    }
    float inv = 1.f / fmaxf(sqrtf(nrm), 1e-12f);
#pragma unroll
    for (int c = 0; c < NC; c++) {
        float o = __ldg(&bc[c]);
        float ic = 0.f;
#pragma unroll
        for (int k = 0; k < OUTD; k++) {
            o = fmaf(xw[k], __ldg(&Wc[k * NC + c]), o);
            ic = fmaf(xw[k], g_cn[c * OUTD + k], ic);
        }
        out[(size_t)n * NC + c] = o;
        out[(size_t)NN * NC + (size_t)NN * OUTD + (size_t)n * NC + c] = ic * inv;
    }
}

// ---------------- launch ----------------
extern "C" void kernel_launch(void* const* d_in, const int* in_sizes, int n_in,
                              void* d_out, int out_size) {
    const float* x   = (const float*)d_in[0];
    const int*   ei  = (const int*)d_in[1];
    const float* W1  = (const float*)d_in[2];
    const float* as1 = (const float*)d_in[3];
    const float* ad1 = (const float*)d_in[4];
    const float* b1  = (const float*)d_in[5];
    const float* W2  = (const float*)d_in[6];
    const float* as2 = (const float*)d_in[7];
    const float* ad2 = (const float*)d_in[8];
    const float* b2  = (const float*)d_in[9];
    const float* Wa  = (const float*)d_in[10];
    const float* ba  = (const float*)d_in[11];
    const float* wv  = (const float*)d_in[12];
    const float* bv  = (const float*)d_in[13];
    const float* ca  = (const float*)d_in[14];
    const float* Wc  = (const float*)d_in[15];
    const float* bc  = (const float*)d_in[16];
    float* out = (float*)d_out;

    int E  = in_sizes[1] / 2;
    int NE = E + NN;

    k_init<<<(NN + 255) / 256, 256>>>();
    k_cn<<<1, 128>>>(ca);

    // CSR build (shared by both layers)
    k_deg<<<(NE + 255) / 256, 256>>>(ei, E, NE);
    k_scan<<<1, 1024>>>();
    k_scatter<<<(NE + 255) / 256, 256>>>(ei, E, NE);

    {
        dim3 g(F1 / 64, (NN + 127) / 128);
        k_gemm1<<<g, 256>>>(x, W1);
    }
    k_att1<<<NN, 128>>>(as1, ad1);
    k_agg1<<<NN, 128>>>(b1);

    {
        dim3 g(OUTD / 64, (NN + 127) / 128);
        k_gemm2<<<g, 256>>>(W2);
    }
    k_att2<<<(NN + 7) / 8, 256>>>(as2, ad2);
    k_agg2<<<(NN + 7) / 8, 256>>>(b2);

    k_scores<<<(NN + 127) / 128, 128>>>(Wa, ba, wv, bv);
    k_rmax<<<64, 256>>>();
    k_rsum<<<64, 256>>>();
    k_final<<<(NN + 127) / 128, 128>>>(Wc, bc, out);
}